// round 1
// baseline (speedup 1.0000x reference)
#include <cuda_runtime.h>
#include <math.h>

// Problem constants
#define NFFT     256
#define HOPSZ    128
#define NBIN     129      // NFFT/2 + 1
#define TOUT     128
#define FOUT     64
#define NFRAMES  1250
#define TSAMP    160000
#define NSIG     512      // 32 * 16

// One block per (signal, output_time). 128 threads.
// Loads the 384 samples covering frames f0 and f0+1 (hop overlap),
// computes both rFFTs with ONE 256-pt complex FFT (pack real pair),
// log-magnitude + clip, freq bilinear (2-tap), time bilinear (2-tap).
__global__ __launch_bounds__(128) void raw_to_spec_kernel(
    const float* __restrict__ x, float* __restrict__ out)
{
    __shared__ float2 z[NFFT];       // FFT workspace
    __shared__ float2 tw[128];       // twiddles exp(-2*pi*i*j/256)
    __shared__ float  samp[384];     // raw samples for the two frames
    __shared__ float  lm0[NBIN];     // clipped log-mag, frame f0
    __shared__ float  lm1[NBIN];     // clipped log-mag, frame f0+1

    const int tid = threadIdx.x;
    const int bid = blockIdx.x;      // = sig*128 + it
    const int it  = bid & 127;
    const int sig = bid >> 7;

    // half-pixel-center source coordinate along time
    const float srct = (it + 0.5f) * ((float)NFRAMES / (float)TOUT) - 0.5f;
    const int   f0   = (int)floorf(srct);        // in [4, 1244] -> no clamping needed
    const float wt   = srct - (float)f0;

    const float* xs = x + (size_t)sig * TSAMP + (size_t)f0 * HOPSZ;

    // load 384 contiguous samples (coalesced; frame end <= 159616 < 160000)
    samp[tid]       = xs[tid];
    samp[tid + 128] = xs[tid + 128];
    samp[tid + 256] = xs[tid + 256];

    // twiddle table: tw[j] = exp(-2*pi*i*j/256)
    {
        float s, c;
        sincospif(-(float)tid / 128.0f, &s, &c);
        tw[tid] = make_float2(c, s);
    }
    __syncthreads();

    // pack z[n] = win[n]*frame0[n] + i * win[n]*frame1[n], bit-reversed store (DIT)
    #pragma unroll
    for (int q = 0; q < 2; q++) {
        int n = tid + q * 128;
        float w = 0.5f - 0.5f * cospif((float)n / 128.0f);  // periodic Hann
        float a = w * samp[n];
        float b = w * samp[n + HOPSZ];
        int r = __brev((unsigned)n) >> 24;
        z[r] = make_float2(a, b);
    }
    __syncthreads();

    // 8 radix-2 DIT stages, 128 butterflies per stage (one per thread)
    #pragma unroll
    for (int s = 0; s < 8; s++) {
        int half = 1 << s;
        int grp  = tid >> s;
        int pos  = tid & (half - 1);
        int i0   = (grp << (s + 1)) + pos;
        int i1   = i0 + half;
        float2 w = tw[pos << (7 - s)];
        float2 u = z[i0];
        float2 v = z[i1];
        float vr = v.x * w.x - v.y * w.y;
        float vi = v.x * w.y + v.y * w.x;
        z[i0] = make_float2(u.x + vr, u.y + vi);
        z[i1] = make_float2(u.x - vr, u.y - vi);
        __syncthreads();
    }

    // Untangle the two real spectra:
    //   A[k] = (Z[k] + conj(Z[N-k]))/2   (frame0)
    //   B[k] = (Z[k] - conj(Z[N-k]))/(2i) (frame1)
    // then clipped log-magnitude.
    for (int k = tid; k < NBIN; k += 128) {
        int nk = (NFFT - k) & (NFFT - 1);
        float2 zk = z[k];
        float2 zn = z[nk];
        float ar = 0.5f * (zk.x + zn.x);
        float ai = 0.5f * (zk.y - zn.y);
        float br = 0.5f * (zk.y + zn.y);
        float bi = 0.5f * (zn.x - zk.x);
        float l0 = logf(sqrtf(ar * ar + ai * ai) + 1e-9f);
        float l1 = logf(sqrtf(br * br + bi * bi) + 1e-9f);
        lm0[k] = fminf(fmaxf(l0, -12.0f), 12.0f);
        lm1[k] = fminf(fmaxf(l1, -12.0f), 12.0f);
    }
    __syncthreads();

    // freq bilinear (interior everywhere: srcf in [0.507, 127.49]) + time blend
    if (tid < FOUT) {
        float srcf = (tid + 0.5f) * ((float)NBIN / (float)FOUT) - 0.5f;
        int   c0   = (int)floorf(srcf);
        float wf   = srcf - (float)c0;
        float v0 = lm0[c0] + wf * (lm0[c0 + 1] - lm0[c0]);
        float v1 = lm1[c0] + wf * (lm1[c0 + 1] - lm1[c0]);
        float v  = v0 + wt * (v1 - v0);
        v = fminf(fmaxf(v, -12.0f), 12.0f);
        out[(size_t)bid * FOUT + tid] = v;
    }
}

extern "C" void kernel_launch(void* const* d_in, const int* in_sizes, int n_in,
                              void* d_out, int out_size)
{
    const float* x = (const float*)d_in[0];
    float* out = (float*)d_out;
    (void)in_sizes; (void)n_in; (void)out_size;
    raw_to_spec_kernel<<<NSIG * TOUT, 128>>>(x, out);
}

// round 2
// speedup vs baseline: 3.5185x; 3.5185x over previous
#include <cuda_runtime.h>
#include <math.h>

// Problem constants
#define NFFT     256
#define HOPSZ    128
#define NBIN     129
#define TOUT     128
#define FOUT     64
#define NFRAMES  1250
#define TSAMP    160000
#define NSIG     512
#define WARPS_PER_BLOCK 8

__device__ __forceinline__ float2 cmul(float2 a, float2 b) {
    return make_float2(a.x * b.x - a.y * b.y, a.x * b.y + a.y * b.x);
}
__device__ __forceinline__ float2 cadd(float2 a, float2 b) {
    return make_float2(a.x + b.x, a.y + b.y);
}
__device__ __forceinline__ float2 csub(float2 a, float2 b) {
    return make_float2(a.x - b.x, a.y - b.y);
}
__device__ __forceinline__ float clip12(float v) {
    return fminf(fmaxf(v, -12.0f), 12.0f);
}

// One WARP per (signal, output_time) tile. 256-pt packed complex FFT:
//   N = 8 (per-lane registers) x 32 (across lanes via shfl).
// No __syncthreads anywhere; FFT is entirely register/shuffle resident.
__global__ __launch_bounds__(32 * WARPS_PER_BLOCK)
void raw_to_spec_kernel(const float* __restrict__ x, float* __restrict__ out)
{
    // per-warp |A|^2,|B|^2 slab, layout addr = k2 + 17*k1  (k = k1 + 8*k2, k<=128)
    __shared__ float2 sq[WARPS_PER_BLOCK][8 * 17];

    const int lane = threadIdx.x & 31;
    const int wl   = threadIdx.x >> 5;
    const int tile = blockIdx.x * WARPS_PER_BLOCK + wl;   // sig*128 + it
    const int it   = tile & 127;
    const int sig  = tile >> 7;

    const float srct = (it + 0.5f) * ((float)NFRAMES / (float)TOUT) - 0.5f; // in [4.38,1244.6]
    const int   f0   = (int)srct;
    const float wt   = srct - (float)f0;

    const float* xs = x + (size_t)sig * TSAMP + (size_t)f0 * HOPSZ;

    // --- load 384 samples: lane + 32*j, j=0..11 (frame0 = j 0..7, frame1 = j 4..11) ---
    float s[12];
    #pragma unroll
    for (int j = 0; j < 12; j++) s[j] = xs[lane + 32 * j];

    // --- master twiddles: m1 = e^{-2*pi*i*lane/256}, m32 = m1^8 = e^{-2*pi*i*lane/32} ---
    float2 m1;
    sincospif(-(float)lane * (1.0f / 128.0f), &m1.y, &m1.x);
    float2 mt  = cmul(m1, m1);
    mt = cmul(mt, mt);
    const float2 m32 = cmul(mt, mt);

    // --- window + pack: a[n1] = w(n)*x0[n] + i*w(n)*x1[n], n = lane + 32*n1 ---
    // w(n) = 0.5 - 0.5*cos(2*pi*n/256); cos(2pi n/256) = m1.x*C[n1] + m1.y*S[n1]
    const float R = 0.70710678118654752f;
    const float WC[8] = {1.f,  R, 0.f, -R, -1.f, -R,  0.f,  R};
    const float WS[8] = {0.f,  R, 1.f,  R,  0.f, -R, -1.f, -R};
    float2 a[8];
    #pragma unroll
    for (int n1 = 0; n1 < 8; n1++) {
        float w = 0.5f - 0.5f * (m1.x * WC[n1] + m1.y * WS[n1]);
        a[n1] = make_float2(w * s[n1], w * s[n1 + 4]);
    }

    // --- step A: 8-point DIF FFT in registers (natural in, natural out y[k1]) ---
    float2 t0 = cadd(a[0], a[4]), t4 = csub(a[0], a[4]);
    float2 t1 = cadd(a[1], a[5]), t5 = csub(a[1], a[5]);
    float2 t2 = cadd(a[2], a[6]), t6 = csub(a[2], a[6]);
    float2 t3 = cadd(a[3], a[7]), t7 = csub(a[3], a[7]);
    // odd-branch twiddles: t5 *= W8^1 = (R,-R); t6 *= -i; t7 *= W8^3 = (-R,-R)
    t5 = make_float2(R * (t5.x + t5.y), R * (t5.y - t5.x));
    t6 = make_float2(t6.y, -t6.x);
    t7 = make_float2(R * (t7.y - t7.x), -R * (t7.x + t7.y));
    float2 v[8];
    {   // even 4pt on t0..t3 -> y0,y2,y4,y6
        float2 u0 = cadd(t0, t2), u2 = csub(t0, t2);
        float2 u1 = cadd(t1, t3), u3 = csub(t1, t3);
        v[0] = cadd(u0, u1);
        v[4] = csub(u0, u1);
        v[2] = make_float2(u2.x + u3.y, u2.y - u3.x);   // u2 - i*u3
        v[6] = make_float2(u2.x - u3.y, u2.y + u3.x);   // u2 + i*u3
    }
    {   // odd 4pt on t4..t7 -> y1,y3,y5,y7
        float2 u0 = cadd(t4, t6), u2 = csub(t4, t6);
        float2 u1 = cadd(t5, t7), u3 = csub(t5, t7);
        v[1] = cadd(u0, u1);
        v[5] = csub(u0, u1);
        v[3] = make_float2(u2.x + u3.y, u2.y - u3.x);
        v[7] = make_float2(u2.x - u3.y, u2.y + u3.x);
    }

    // --- step B: y[k1] *= m1^k1 ---
    {
        float2 acc = m1;
        v[1] = cmul(v[1], acc);
        #pragma unroll
        for (int k = 2; k < 8; k++) { acc = cmul(acc, m1); v[k] = cmul(v[k], acc); }
    }

    // --- step C: 32-pt cross-lane DIF FFT (5 shfl_xor stages) for each register ---
    // After this, lane l holds Z[k1 + 8*k2] with k2 = bitrev5(l).
    #pragma unroll
    for (int st = 0; st < 5; st++) {
        const int half = 16 >> st;
        const int p    = lane & (half - 1);
        const int src  = p << st;                       // W_{2*half}^p = m32[src]
        float wx = __shfl_sync(0xffffffffu, m32.x, src);
        float wy = __shfl_sync(0xffffffffu, m32.y, src);
        const bool up  = (lane & half) != 0;
        const float sgn = up ? -1.0f : 1.0f;
        if (!up) { wx = 1.0f; wy = 0.0f; }
        #pragma unroll
        for (int r = 0; r < 8; r++) {
            float ox = __shfl_xor_sync(0xffffffffu, v[r].x, half);
            float oy = __shfl_xor_sync(0xffffffffu, v[r].y, half);
            float tx = fmaf(sgn, v[r].x, ox);           // low: v+o ; high: o-v
            float ty = fmaf(sgn, v[r].y, oy);
            v[r].x = tx * wx - ty * wy;
            v[r].y = tx * wy + ty * wx;
        }
    }

    // --- untangle: need conj-partner Z[(256-k) mod 256] ---
    const int k2 = __brev((unsigned)lane) >> 27;        // bitrev5(lane)
    float2 c[8];
    const int lsrc = lane ^ 31;                         // partner lane for k1>=1
    #pragma unroll
    for (int k1 = 1; k1 < 8; k1++) {
        c[k1].x = __shfl_sync(0xffffffffu, v[8 - k1].x, lsrc);
        c[k1].y = __shfl_sync(0xffffffffu, v[8 - k1].y, lsrc);
    }
    const int src0 = __brev((unsigned)((32 - k2) & 31)) >> 27;
    c[0].x = __shfl_sync(0xffffffffu, v[0].x, src0);
    c[0].y = __shfl_sync(0xffffffffu, v[0].y, src0);

    // --- |A|^2, |B|^2 for bins k<=128, store to per-warp slab ---
    #pragma unroll
    for (int k1 = 0; k1 < 8; k1++) {
        int k = k1 + 8 * k2;
        if (k <= 128) {
            float ar = 0.5f * (v[k1].x + c[k1].x);
            float ai = 0.5f * (v[k1].y - c[k1].y);
            float br = 0.5f * (v[k1].y + c[k1].y);
            float bi = 0.5f * (c[k1].x - v[k1].x);
            sq[wl][k2 + 17 * k1] = make_float2(ar * ar + ai * ai, br * br + bi * bi);
        }
    }
    __syncwarp();

    // --- log-mag + clip + freq/time bilinear, 2 outputs per lane ---
    #pragma unroll
    for (int q = 0; q < 2; q++) {
        int fo = lane + 32 * q;
        float srcf = (fo + 0.5f) * ((float)NBIN / (float)FOUT) - 0.5f;  // [0.507,127.49]
        int   c0   = (int)srcf;
        float wf   = srcf - (float)c0;
        int c1i = c0 + 1;
        float2 qa = sq[wl][(c0  >> 3) + 17 * (c0  & 7)];
        float2 qb = sq[wl][(c1i >> 3) + 17 * (c1i & 7)];
        float l0a = clip12(__logf(sqrtf(qa.x) + 1e-9f));
        float l1a = clip12(__logf(sqrtf(qa.y) + 1e-9f));
        float l0b = clip12(__logf(sqrtf(qb.x) + 1e-9f));
        float l1b = clip12(__logf(sqrtf(qb.y) + 1e-9f));
        float v0 = l0a + wf * (l0b - l0a);
        float v1 = l1a + wf * (l1b - l1a);
        float vo = v0 + wt * (v1 - v0);
        out[(size_t)tile * FOUT + fo] = clip12(vo);
    }
}

extern "C" void kernel_launch(void* const* d_in, const int* in_sizes, int n_in,
                              void* d_out, int out_size)
{
    const float* x = (const float*)d_in[0];
    float* out = (float*)d_out;
    (void)in_sizes; (void)n_in; (void)out_size;
    const int tiles = NSIG * TOUT;                       // 65536 warps
    raw_to_spec_kernel<<<tiles / WARPS_PER_BLOCK, 32 * WARPS_PER_BLOCK>>>(x, out);
}

// round 8
// speedup vs baseline: 3.7553x; 1.0673x over previous
#include <cuda_runtime.h>
#include <math.h>

#define NFFT     256
#define HOPSZ    128
#define NBIN     129
#define TOUT     128
#define FOUT     64
#define NFRAMES  1250
#define TSAMP    160000
#define NSIG     512
#define WARPS_PER_BLOCK 8
#define SLAB     133        // bins 0..128 at addr (k&31) + 33*(k>>5)

__device__ __forceinline__ float2 cmul(float2 a, float2 b) {
    return make_float2(a.x * b.x - a.y * b.y, a.x * b.y + a.y * b.x);
}
__device__ __forceinline__ float2 cadd(float2 a, float2 b) {
    return make_float2(a.x + b.x, a.y + b.y);
}
__device__ __forceinline__ float2 csub(float2 a, float2 b) {
    return make_float2(a.x - b.x, a.y - b.y);
}
__device__ __forceinline__ float clip12(float v) {
    return fminf(fmaxf(v, -12.0f), 12.0f);
}

// One WARP per (signal, output_time) tile.
// 256-pt packed complex FFT, decomposition n = r + 8*l:
//   step 1: 32-pt cross-lane DIF FFT (5 shfl stages; last two degenerate)
//   step 2: twiddle W256^(r*k2)
//   step 3: 8-pt register FFT
// Output bin k = k2 + 32*k3 -> only regs k3=0..3 (+ lane-0 specials) feed the resize.
__global__ __launch_bounds__(32 * WARPS_PER_BLOCK)
void raw_to_spec_kernel(const float* __restrict__ x, float* __restrict__ out)
{
    __shared__ float2 sq[WARPS_PER_BLOCK][SLAB];   // (logmag frame0, logmag frame1)

    const int lane = threadIdx.x & 31;
    const int wl   = threadIdx.x >> 5;
    const int tile = blockIdx.x * WARPS_PER_BLOCK + wl;   // sig*128 + it
    const int it   = tile & 127;
    const int sig  = tile >> 7;

    const float srct = (it + 0.5f) * ((float)NFRAMES / (float)TOUT) - 0.5f; // [4.38,1244.6]
    const int   f0   = (int)srct;
    const float wt   = srct - (float)f0;

    const float* xs = x + (size_t)sig * TSAMP + (size_t)f0 * HOPSZ;  // 16B-aligned

    // ---- vectorized loads: lane holds samples n = 8*lane + r (r=0..7) for both frames ----
    const float4* X4 = (const float4*)xs;
    float4 p0 = X4[2 * lane];
    float4 p1 = X4[2 * lane + 1];
    float4 p2 = X4[2 * lane + 32];   // frame1 = xs + 128 floats
    float4 p3 = X4[2 * lane + 33];
    float s0[8] = {p0.x, p0.y, p0.z, p0.w, p1.x, p1.y, p1.z, p1.w};
    float s1[8] = {p2.x, p2.y, p2.z, p2.w, p3.x, p3.y, p3.z, p3.w};

    // ---- master twiddle m32[lane] = e^{-2*pi*i*lane/32} ----
    float2 m32;
    sincospif(-(float)lane * (1.0f / 16.0f), &m32.y, &m32.x);

    // ---- window + pack: a[r] = w(n)*x0[n] + i*w(n)*x1[n], n = r + 8*lane ----
    // cos(2*pi*n/256) = cr*m32.x + sr*m32.y  with (cr,sr)=(cos,sin)(pi*r/128)
    const float WC[8] = {1.0f, 0.9996988186962042f, 0.9987954562051724f, 0.9972904566786902f,
                         0.9951847266721969f, 0.9924795345987101f, 0.9891765099647810f,
                         0.9852776423889412f};
    const float WS[8] = {0.0f, 0.0245412285229123f, 0.0490676743274180f, 0.0735645635996674f,
                         0.0980171403295606f, 0.1224106751992162f, 0.1467304744553618f,
                         0.1709618887603012f};
    float2 a[8];
    #pragma unroll
    for (int r = 0; r < 8; r++) {
        float w = fmaf(-0.5f, WC[r] * m32.x + WS[r] * m32.y, 0.5f);
        a[r] = make_float2(w * s0[r], w * s1[r]);
    }

    // ---- step 1: 32-pt cross-lane DIF FFT over lanes (output lane index = brev5(k2)) ----
    #pragma unroll
    for (int st = 0; st < 3; st++) {
        const int half = 16 >> st;
        const int src  = (lane & (half - 1)) << st;
        float wx = __shfl_sync(0xffffffffu, m32.x, src);
        float wy = __shfl_sync(0xffffffffu, m32.y, src);
        const bool up  = (lane & half) != 0;
        const float sgn = up ? -1.0f : 1.0f;
        if (!up) { wx = 1.0f; wy = 0.0f; }
        #pragma unroll
        for (int r = 0; r < 8; r++) {
            float ox = __shfl_xor_sync(0xffffffffu, a[r].x, half);
            float oy = __shfl_xor_sync(0xffffffffu, a[r].y, half);
            float tx = fmaf(sgn, a[r].x, ox);
            float ty = fmaf(sgn, a[r].y, oy);
            a[r].x = tx * wx - ty * wy;
            a[r].y = tx * wy + ty * wx;
        }
    }
    {   // stage 3: half=2, twiddle is 1 or -i  ->  select/negate only
        const float sgn = (lane & 2) ? -1.0f : 1.0f;
        const bool rot  = (lane & 3) == 3;           // high half with p=1: multiply by -i
        #pragma unroll
        for (int r = 0; r < 8; r++) {
            float ox = __shfl_xor_sync(0xffffffffu, a[r].x, 2);
            float oy = __shfl_xor_sync(0xffffffffu, a[r].y, 2);
            float tx = fmaf(sgn, a[r].x, ox);
            float ty = fmaf(sgn, a[r].y, oy);
            a[r].x = rot ?  ty : tx;
            a[r].y = rot ? -tx : ty;
        }
    }
    {   // stage 4: half=1, twiddle = 1 for all
        const float sgn = (lane & 1) ? -1.0f : 1.0f;
        #pragma unroll
        for (int r = 0; r < 8; r++) {
            float ox = __shfl_xor_sync(0xffffffffu, a[r].x, 1);
            float oy = __shfl_xor_sync(0xffffffffu, a[r].y, 1);
            a[r].x = fmaf(sgn, a[r].x, ox);
            a[r].y = fmaf(sgn, a[r].y, oy);
        }
    }

    // lane now holds G_r[k2] with k2 = brev5(lane)
    const int k2 = __brev((unsigned)lane) >> 27;

    // ---- step 2: twiddle H_r = G_r * b^r,  b = e^{-2*pi*i*k2/256} ----
    {
        float2 b;
        sincospif(-(float)k2 * (1.0f / 128.0f), &b.y, &b.x);
        float2 acc = b;
        a[1] = cmul(a[1], acc);
        #pragma unroll
        for (int r = 2; r < 8; r++) { acc = cmul(acc, b); a[r] = cmul(a[r], acc); }
    }

    // ---- step 3: 8-pt register DFT (natural in r -> natural out k3) ----
    float2 y[8];
    {
        const float R = 0.70710678118654752f;
        float2 t0 = cadd(a[0], a[4]), t4 = csub(a[0], a[4]);
        float2 t1 = cadd(a[1], a[5]), t5 = csub(a[1], a[5]);
        float2 t2 = cadd(a[2], a[6]), t6 = csub(a[2], a[6]);
        float2 t3 = cadd(a[3], a[7]), t7 = csub(a[3], a[7]);
        t5 = make_float2(R * (t5.x + t5.y), R * (t5.y - t5.x));
        t6 = make_float2(t6.y, -t6.x);
        t7 = make_float2(R * (t7.y - t7.x), -R * (t7.x + t7.y));
        {   // even outputs
            float2 u0 = cadd(t0, t2), u2 = csub(t0, t2);
            float2 u1 = cadd(t1, t3), u3 = csub(t1, t3);
            y[0] = cadd(u0, u1);
            y[4] = csub(u0, u1);
            y[2] = make_float2(u2.x + u3.y, u2.y - u3.x);
            y[6] = make_float2(u2.x - u3.y, u2.y + u3.x);
        }
        {   // odd outputs
            float2 u0 = cadd(t4, t6), u2 = csub(t4, t6);
            float2 u1 = cadd(t5, t7), u3 = csub(t5, t7);
            y[1] = cadd(u0, u1);
            y[5] = csub(u0, u1);
            y[3] = make_float2(u2.x + u3.y, u2.y - u3.x);
            y[7] = make_float2(u2.x - u3.y, u2.y + u3.x);
        }
    }
    // lane holds X[k2 + 32*k3] in y[k3]

    // ---- untangle + log-mag + clip for bins k = k2 + 32*k3, k3 = 0..3 ----
    // conj partner of k: (32-k2) + 32*(7-k3) for k2>=1  -> reg 7-k3, lane brev5(32-k2)
    const int lsrc = __brev((unsigned)((32 - k2) & 31)) >> 27;
    #pragma unroll
    for (int k3 = 0; k3 < 4; k3++) {
        float cx = __shfl_sync(0xffffffffu, y[7 - k3].x, lsrc);
        float cy = __shfl_sync(0xffffffffu, y[7 - k3].y, lsrc);
        if (lane == 0) {            // k2 == 0: partner is local reg (8-k3)&7
            cx = y[(8 - k3) & 7].x;
            cy = y[(8 - k3) & 7].y;
        }
        float ar = 0.5f * (y[k3].x + cx);
        float ai = 0.5f * (y[k3].y - cy);
        float br = 0.5f * (y[k3].y + cy);
        float bi = 0.5f * (cx - y[k3].x);
        float la = clip12(__logf(sqrtf(ar * ar + ai * ai) + 1e-9f));
        float lb = clip12(__logf(sqrtf(br * br + bi * bi) + 1e-9f));
        sq[wl][k2 + 33 * k3] = make_float2(la, lb);
    }
    if (lane == 0) {                // bin 128 = X[128] = y[4] (real spectra: A=Re, B=Im)
        float la = clip12(__logf(fabsf(y[4].x) + 1e-9f));
        float lb = clip12(__logf(fabsf(y[4].y) + 1e-9f));
        sq[wl][132] = make_float2(la, lb);
    }
    __syncwarp();

    // ---- bilinear resize: freq 2-tap then time 2-tap (all interior) ----
    float* po = out + (size_t)tile * FOUT;
    #pragma unroll
    for (int q = 0; q < 2; q++) {
        int fo = lane + 32 * q;
        float srcf = (fo + 0.5f) * ((float)NBIN / (float)FOUT) - 0.5f;  // [0.507,127.49]
        int   c0   = (int)srcf;
        float wf   = srcf - (float)c0;
        int   c1   = c0 + 1;
        float2 q0 = sq[wl][(c0 & 31) + 33 * (c0 >> 5)];
        float2 q1 = sq[wl][(c1 & 31) + 33 * (c1 >> 5)];
        float v0 = fmaf(wf, q1.x - q0.x, q0.x);
        float v1 = fmaf(wf, q1.y - q0.y, q0.y);
        po[fo] = clip12(fmaf(wt, v1 - v0, v0));
    }
}

extern "C" void kernel_launch(void* const* d_in, const int* in_sizes, int n_in,
                              void* d_out, int out_size)
{
    const float* x = (const float*)d_in[0];
    float* out = (float*)d_out;
    (void)in_sizes; (void)n_in; (void)out_size;
    const int tiles = NSIG * TOUT;
    raw_to_spec_kernel<<<tiles / WARPS_PER_BLOCK, 32 * WARPS_PER_BLOCK>>>(x, out);
}